// round 11
// baseline (speedup 1.0000x reference)
#include <cuda_runtime.h>
#include <math.h>
#include <stdint.h>

#define BB   4
#define SSEQ 2048
#define DD   512
#define HH   8
#define DHH  64
#define E3   1536

// Scratch (allocation-free rule: __device__ globals)
__device__ float g_q[BB*HH*SSEQ*DHH];    // [b,h,s,dh]
__device__ float g_k[BB*HH*SSEQ*DHH];
__device__ float g_v[BB*HH*SSEQ*DHH];
__device__ float g_attn[BB*SSEQ*DD];     // [b,s,d]
__device__ int   g_cnt[BB];              // active-key count per batch
__device__ int   g_idx[BB*SSEQ];         // active key indices (unordered)

// ---------------------------------------------------------------------------
// TF32 mma.sync helpers (plain sm_80+ PTX)
// ---------------------------------------------------------------------------
__device__ __forceinline__ uint32_t f2tf32(float x) {
    uint32_t y;
    asm("cvt.rna.tf32.f32 %0, %1;" : "=r"(y) : "f"(x));
    return y;
}
// Register-time round-to-nearest for raw fp32 bits fed to tf32 MMA.
#define RNA(x) ((x) + 0x1000u)

__device__ __forceinline__ void mma_tf32(float (&d)[4], const uint32_t (&a)[4],
                                         const uint32_t (&b)[2]) {
    asm volatile("mma.sync.aligned.m16n8k8.row.col.f32.tf32.tf32.f32 "
                 "{%0,%1,%2,%3}, {%4,%5,%6,%7}, {%8,%9}, {%0,%1,%2,%3};"
                 : "+f"(d[0]), "+f"(d[1]), "+f"(d[2]), "+f"(d[3])
                 : "r"(a[0]), "r"(a[1]), "r"(a[2]), "r"(a[3]),
                   "r"(b[0]), "r"(b[1]));
}
__device__ __forceinline__ uint32_t smem_u32(const void* p) {
    uint32_t a;
    asm("{ .reg .u64 t; cvta.to.shared.u64 t, %1; cvt.u32.u64 %0, t; }"
        : "=r"(a) : "l"(p));
    return a;
}

// Fast 2^x for x <= 0 on the FMA pipe (no MUFU). Rel err ~4e-5.
__device__ __forceinline__ float fexp2(float x) {
    x = fmaxf(x, -126.0f);
    const float z = x + 12582912.0f;                       // 1.5*2^23
    const int   n = (__float_as_int(z) & 0x7FFFFF) - 0x400000;
    const float f = x - (z - 12582912.0f);
    float p = fmaf(fmaf(fmaf(fmaf(0.00961813f, f, 0.05550411f),
                             f, 0.24022651f), f, 0.69314718f), f, 1.0f);
    return __int_as_float(__float_as_int(p) + (n << 23));
}

// ---------------------------------------------------------------------------
// Projection GEMMs: 128x128 CTA tile, 8 warps (2M x 4N), warp tile 64x32.
// cp.async 3-stage pipeline, k-chunk 32, stride-36 SMEM (108KB -> 2 CTAs/SM).
// ---------------------------------------------------------------------------
#define GST 36
#define KC  32
#define NCH (DD/KC)          // 16 chunks
#define NST 3                // pipeline stages
#define GEMM_TILE_U32 (128*GST)
#define GEMM_SMEM_BYTES (NST * 2 * GEMM_TILE_U32 * 4)   // 110592

// Prefetch one k-chunk of A and B into stage ch%NST.
__device__ __forceinline__ void gemm_prefetch(const float* __restrict__ Ag,
                                              const float* __restrict__ Bg,
                                              int ch, uint32_t a_byte,
                                              uint32_t b_byte, int tid) {
    const uint32_t so = (uint32_t)((ch % NST) * 2 * GEMM_TILE_U32 * 4);
    #pragma unroll
    for (int it = 0; it < 4; it++) {
        const int i = tid + it * 256;
        const int r = i >> 3;               // row 0..127
        const int c = (i & 7) * 16;         // byte chunk within 128B row
        const void* ga = (const char*)(Ag + (size_t)r * DD + ch * KC) + c;
        const void* gb = (const char*)(Bg + (size_t)r * DD + ch * KC) + c;
        const uint32_t da = a_byte + so + (uint32_t)r * (GST*4) + c;
        const uint32_t db = b_byte + so + (uint32_t)r * (GST*4) + c;
        asm volatile("cp.async.cg.shared.global [%0], [%1], 16;" :: "r"(da), "l"(ga));
        asm volatile("cp.async.cg.shared.global [%0], [%1], 16;" :: "r"(db), "l"(gb));
    }
    asm volatile("cp.async.commit_group;" ::: "memory");
}

__device__ __forceinline__ void mma_mainloop(const float* __restrict__ Ag,
                                             const float* __restrict__ Bg,
                                             uint32_t* smu,
                                             float acc[4][4][4]) {
    const int tid = threadIdx.x;
    const int wid = tid >> 5, lane = tid & 31;
    const int wm = wid >> 2, wn = wid & 3;
    const int lr = lane >> 2, lc = lane & 3;
    const uint32_t sb = smem_u32(smu);
    const uint32_t a_byte = sb;
    const uint32_t b_byte = sb + GEMM_TILE_U32 * 4;

    gemm_prefetch(Ag, Bg, 0, a_byte, b_byte, tid);
    gemm_prefetch(Ag, Bg, 1, a_byte, b_byte, tid);

    for (int ch = 0; ch < NCH; ch++) {
        gemm_prefetch(Ag, Bg, (ch + 2 < NCH) ? ch + 2 : NCH - 1,
                      a_byte, b_byte, tid);
        asm volatile("cp.async.wait_group 2;" ::: "memory");   // chunk ch landed
        __syncthreads();

        const uint32_t* As = smu + (ch % NST) * 2 * GEMM_TILE_U32;
        const uint32_t* Bs = As + GEMM_TILE_U32;

        #pragma unroll
        for (int ks = 0; ks < KC; ks += 8) {
            uint32_t a[4][4], b[4][2];
            #pragma unroll
            for (int mf = 0; mf < 4; mf++) {
                const uint32_t* p = As + (wm*64 + mf*16 + lr) * GST + ks + lc;
                a[mf][0] = RNA(p[0]);
                a[mf][1] = RNA(p[8*GST]);
                a[mf][2] = RNA(p[4]);
                a[mf][3] = RNA(p[8*GST + 4]);
            }
            #pragma unroll
            for (int nf = 0; nf < 4; nf++) {
                const uint32_t* p = Bs + (wn*32 + nf*8 + lr) * GST + ks + lc;
                b[nf][0] = RNA(p[0]);
                b[nf][1] = RNA(p[4]);
            }
            #pragma unroll
            for (int mf = 0; mf < 4; mf++)
                #pragma unroll
                for (int nf = 0; nf < 4; nf++)
                    mma_tf32(acc[mf][nf], a[mf], b[nf]);
        }
        __syncthreads();   // reads of stage ch%NST done before ch+3 prefetch
    }
}

__global__ __launch_bounds__(256, 2) void qkv_mma(const float* __restrict__ X,
                                                  const float* __restrict__ W,
                                                  const float* __restrict__ bias) {
    extern __shared__ uint32_t smu[];
    const int m0 = blockIdx.y << 7, n0 = blockIdx.x << 7;
    float acc[4][4][4] = {};
    mma_mainloop(X + (size_t)m0 * DD, W + (size_t)n0 * DD, smu, acc);

    const int tid = threadIdx.x;
    const int wid = tid >> 5, lane = tid & 31;
    const int wm = wid >> 2, wn = wid & 3;
    const int lr = lane >> 2, lc = lane & 3;

    #pragma unroll
    for (int mf = 0; mf < 4; mf++) {
        #pragma unroll
        for (int nf = 0; nf < 4; nf++) {
            const int cb = n0 + wn*32 + nf*8 + 2*lc;     // even
            const int h   = cb / 192;
            const int rr  = cb - h * 192;
            const int sel = rr >> 6;
            const int dh0 = rr & 63;
            float* gbase = (sel == 0 ? g_q : sel == 1 ? g_k : g_v);
            const float b0 = bias[cb], b1 = bias[cb + 1];
            #pragma unroll
            for (int half = 0; half < 2; half++) {
                const int row = m0 + wm*64 + mf*16 + lr + 8*half;
                const int bI = row >> 11, sI = row & (SSEQ - 1);
                float2 o;
                o.x = acc[mf][nf][2*half + 0] + b0;
                o.y = acc[mf][nf][2*half + 1] + b1;
                *(float2*)(gbase + ((size_t)(bI*HH + h)*SSEQ + sI)*DHH + dh0) = o;
            }
        }
    }
}

__global__ __launch_bounds__(256, 2) void out_mma(const float* __restrict__ W,
                                                  const float* __restrict__ bias,
                                                  float* __restrict__ Out) {
    extern __shared__ uint32_t smu[];
    const int m0 = blockIdx.y << 7, n0 = blockIdx.x << 7;
    float acc[4][4][4] = {};
    mma_mainloop(g_attn + (size_t)m0 * DD, W + (size_t)n0 * DD, smu, acc);

    const int tid = threadIdx.x;
    const int wid = tid >> 5, lane = tid & 31;
    const int wm = wid >> 2, wn = wid & 3;
    const int lr = lane >> 2, lc = lane & 3;

    #pragma unroll
    for (int mf = 0; mf < 4; mf++) {
        #pragma unroll
        for (int nf = 0; nf < 4; nf++) {
            const int cb = n0 + wn*32 + nf*8 + 2*lc;
            const float b0 = bias[cb], b1 = bias[cb + 1];
            #pragma unroll
            for (int half = 0; half < 2; half++) {
                const int row = m0 + wm*64 + mf*16 + lr + 8*half;
                float2 o;
                o.x = acc[mf][nf][2*half + 0] + b0;
                o.y = acc[mf][nf][2*half + 1] + b1;
                *(float2*)(Out + (size_t)row * DD + cb) = o;
            }
        }
    }
}

// ---------------------------------------------------------------------------
// Mask compaction: one block per batch, self-zeroing (exact: softmax is
// order-invariant; dropped keys would carry weight exp(NEG - max) == 0).
// ---------------------------------------------------------------------------
__global__ __launch_bounds__(1024) void compact_b(const int* __restrict__ mask) {
    const int b = blockIdx.x;
    if (threadIdx.x == 0) g_cnt[b] = 0;
    __syncthreads();
    #pragma unroll
    for (int i = threadIdx.x; i < SSEQ; i += 1024) {
        if (mask[b * SSEQ + i] != 0) {
            const int p = atomicAdd(&g_cnt[b], 1);
            g_idx[b * SSEQ + p] = i;
        }
    }
}

// ---------------------------------------------------------------------------
// Kernel 2: flash attention, tf32 mma.sync, warp tile 16 q-rows x 64 keys.
// P never touches SMEM: the S-accumulator register layout is permuted into
// the PV A-fragment layout with quad shuffles. SMEM = Q + double-buffered
// K/V = 104 KB -> 2 CTAs/SM. CTA = 8 warps = 128 q-rows.
// grid: (B*H = 32, S/128 = 16)
// ---------------------------------------------------------------------------
#define QST 68   // Qs row stride (conflict-free fragment access)
#define KST 68   // Ks row stride [key][dh]
#define VST 72   // Vs row stride [key][dh]; 72%32=8 -> conflict-free B frags
#define ATTN_SMEM_BYTES ((128*QST + 2*64*KST + 2*64*VST) * 4)   // 106496

// Full-tile cp.async prefetch: 64 rows x 256 B each for K and V.
__device__ __forceinline__ void prefetch_tile(const float* Kbh, const float* Vbh,
                                              const int* idx, int t, int L,
                                              uint32_t ks_byte, uint32_t vs_byte,
                                              int tid) {
    const uint32_t bo = (uint32_t)((t & 1) * 64);
    #pragma unroll
    for (int it = 0; it < 4; it++) {
        const int i = tid + it * 256;
        const int r = i >> 4;               // key row 0..63
        const int ch = (i & 15) * 16;       // byte chunk within 256B row
        const int rr = (t << 6) + r;
        const int kr = idx[rr < L ? rr : L - 1];
        const void* gk = (const char*)(Kbh + (size_t)kr * DHH) + ch;
        const void* gv = (const char*)(Vbh + (size_t)kr * DHH) + ch;
        const uint32_t dk = ks_byte + (bo + (uint32_t)r) * (KST*4) + ch;
        const uint32_t dv = vs_byte + (bo + (uint32_t)r) * (VST*4) + ch;
        asm volatile("cp.async.cg.shared.global [%0], [%1], 16;" :: "r"(dk), "l"(gk));
        asm volatile("cp.async.cg.shared.global [%0], [%1], 16;" :: "r"(dv), "l"(gv));
    }
    asm volatile("cp.async.commit_group;" ::: "memory");
}

__global__ __launch_bounds__(256, 2) void attn_mma() {
    extern __shared__ uint32_t smu[];
    uint32_t* Qs  = smu;                     // [128][QST] tf32
    uint32_t* KsB = smu + 128*QST;           // [2][64][KST] fp32 (raw)
    uint32_t* VsB = KsB + 2*64*KST;          // [2][64][VST] fp32 (raw)
    const uint32_t sb = smem_u32(smu);
    const uint32_t ks_byte = sb + 128*QST*4;
    const uint32_t vs_byte = ks_byte + 2*64*KST*4;

    const int tid = threadIdx.x;
    const int wid = tid >> 5, lane = tid & 31;
    const int lr = lane >> 2, lc = lane & 3;
    const int bh = blockIdx.x;
    const int bI = bh >> 3, h = bh & 7;
    const int q0 = blockIdx.y << 7;
    const int L  = g_cnt[bI];
    const int* idx = g_idx + bI * SSEQ;
    const float* Kbh = g_k + (size_t)bh * SSEQ * DHH;
    const float* Vbh = g_v + (size_t)bh * SSEQ * DHH;
    const int nT = (L + 63) >> 6;

    prefetch_tile(Kbh, Vbh, idx, 0, L, ks_byte, vs_byte, tid);

    // Load Q tile (128 x 64) as tf32 (overlaps with cp.async flight)
    const float* Qg = g_q + ((size_t)bh * SSEQ + q0) * DHH;
    #pragma unroll
    for (int it = 0; it < 8; it++) {
        const int i = tid + it * 256;
        const int r = i >> 4, c4 = (i & 15) << 2;
        const float4 v = *(const float4*)(Qg + r * DHH + c4);
        uint32_t* p = Qs + r * QST + c4;
        p[0] = f2tf32(v.x); p[1] = f2tf32(v.y);
        p[2] = f2tf32(v.z); p[3] = f2tf32(v.w);
    }

    float o[8][4] = {};
    float m0r = -3.0e38f, m1r = -3.0e38f;
    float l0r = 0.f, l1r = 0.f;
    const float C = 0.18033688f;   // (1/sqrt(64)) * log2(e)
    const int qrow = (wid << 4) + lr;          // this lane's base q-row
    const int srcA = (lane & ~3) | (lc >> 1);  // quad-shuffle sources for PV
    const int srcB = srcA + 2;
    const bool odd = (lc & 1) != 0;

    for (int t = 0; t < nT; t++) {
        prefetch_tile(Kbh, Vbh, idx, (t + 1 < nT) ? t + 1 : nT - 1, L,
                      ks_byte, vs_byte, tid);
        asm volatile("cp.async.wait_group 1;" ::: "memory");   // tile t landed
        __syncthreads();

        const uint32_t* Kc = KsB + (t & 1) * 64 * KST;
        const uint32_t* Vc = VsB + (t & 1) * 64 * VST;
        const int k0 = t << 6;

        // S = Q K^T  (16 rows x 64 keys per warp)
        float s[8][4] = {};
        #pragma unroll
        for (int ks = 0; ks < 8; ks++) {
            uint32_t a[4];
            const uint32_t* pa = Qs + qrow * QST + ks*8 + lc;
            a[0] = pa[0];
            a[1] = pa[8*QST];
            a[2] = pa[4];
            a[3] = pa[8*QST + 4];
            #pragma unroll
            for (int nf = 0; nf < 8; nf++) {
                uint32_t b[2];
                const uint32_t* pb = Kc + (nf*8 + lr) * KST + ks*8 + lc;
                b[0] = pb[0];
                b[1] = pb[4];
                mma_tf32(s[nf], a, b);
            }
        }

        // Scale + mask padding columns
        #pragma unroll
        for (int nf = 0; nf < 8; nf++) {
            const int cb = k0 + nf*8 + 2*lc;
            const bool v0 = cb < L, v1 = (cb + 1) < L;
            s[nf][0] = v0 ? s[nf][0]*C : -3.0e38f;
            s[nf][1] = v1 ? s[nf][1]*C : -3.0e38f;
            s[nf][2] = v0 ? s[nf][2]*C : -3.0e38f;
            s[nf][3] = v1 ? s[nf][3]*C : -3.0e38f;
        }

        // Online softmax (row stats across the 4 lanes of each row group)
        float pm0 = -3.0e38f, pm1 = -3.0e38f;
        #pragma unroll
        for (int nf = 0; nf < 8; nf++) {
            pm0 = fmaxf(pm0, fmaxf(s[nf][0], s[nf][1]));
            pm1 = fmaxf(pm1, fmaxf(s[nf][2], s[nf][3]));
        }
        pm0 = fmaxf(pm0, __shfl_xor_sync(0xffffffffu, pm0, 1));
        pm0 = fmaxf(pm0, __shfl_xor_sync(0xffffffffu, pm0, 2));
        pm1 = fmaxf(pm1, __shfl_xor_sync(0xffffffffu, pm1, 1));
        pm1 = fmaxf(pm1, __shfl_xor_sync(0xffffffffu, pm1, 2));

        const float mn0 = fmaxf(m0r, pm0);
        const float mn1 = fmaxf(m1r, pm1);
        const float al0 = fexp2(m0r - mn0);
        const float al1 = fexp2(m1r - mn1);
        m0r = mn0; m1r = mn1;

        // exp2; keep P in registers (tf32 bits stored as float payload)
        float sum0 = 0.f, sum1 = 0.f;
        #pragma unroll
        for (int nf = 0; nf < 8; nf++) {
            const float p0 = fexp2(s[nf][0] - mn0);
            const float p1 = fexp2(s[nf][1] - mn0);
            const float p2 = fexp2(s[nf][2] - mn1);
            const float p3 = fexp2(s[nf][3] - mn1);
            sum0 += p0 + p1;
            sum1 += p2 + p3;
            s[nf][0] = __uint_as_float(f2tf32(p0));
            s[nf][1] = __uint_as_float(f2tf32(p1));
            s[nf][2] = __uint_as_float(f2tf32(p2));
            s[nf][3] = __uint_as_float(f2tf32(p3));
        }
        sum0 += __shfl_xor_sync(0xffffffffu, sum0, 1);
        sum0 += __shfl_xor_sync(0xffffffffu, sum0, 2);
        sum1 += __shfl_xor_sync(0xffffffffu, sum1, 1);
        sum1 += __shfl_xor_sync(0xffffffffu, sum1, 2);
        l0r = l0r * al0 + sum0;
        l1r = l1r * al1 + sum1;

        #pragma unroll
        for (int nf = 0; nf < 8; nf++) {
            o[nf][0] *= al0; o[nf][1] *= al0;
            o[nf][2] *= al1; o[nf][3] *= al1;
        }

        // O += P V. A-fragment for k-block ks via quad shuffle:
        // accumulator lane lc holds cols {2lc,2lc+1}; frag lane lc needs
        // cols {lc, lc+4} -> broadcast from lanes lc>>1 and (lc>>1)+2.
        #pragma unroll
        for (int ks = 0; ks < 8; ks++) {
            const float q0f = __shfl_sync(0xffffffffu, s[ks][0], srcA);
            const float q1f = __shfl_sync(0xffffffffu, s[ks][1], srcA);
            const float r0f = __shfl_sync(0xffffffffu, s[ks][0], srcB);
            const float r1f = __shfl_sync(0xffffffffu, s[ks][1], srcB);
            const float q2f = __shfl_sync(0xffffffffu, s[ks][2], srcA);
            const float q3f = __shfl_sync(0xffffffffu, s[ks][3], srcA);
            const float r2f = __shfl_sync(0xffffffffu, s[ks][2], srcB);
            const float r3f = __shfl_sync(0xffffffffu, s[ks][3], srcB);
            uint32_t a[4];
            a[0] = __float_as_uint(odd ? q1f : q0f);   // P[lr   ][ks*8+lc  ]
            a[1] = __float_as_uint(odd ? q3f : q2f);   // P[lr+8 ][ks*8+lc  ]
            a[2] = __float_as_uint(odd ? r1f : r0f);   // P[lr   ][ks*8+lc+4]
            a[3] = __float_as_uint(odd ? r3f : r2f);   // P[lr+8 ][ks*8+lc+4]
            #pragma unroll
            for (int nf = 0; nf < 8; nf++) {
                uint32_t b[2];
                const uint32_t* pb = Vc + (ks*8 + lc) * VST + nf*8 + lr;
                b[0] = pb[0];
                b[1] = pb[4*VST];
                mma_tf32(o[nf], a, b);
            }
        }
        __syncthreads();   // all reads of buf t&1 done before t+1 prefetch hits it
    }

    // Epilogue: normalize and write [b,s,d]
    const float inv0 = 1.f / l0r, inv1 = 1.f / l1r;
    const int s0 = q0 + qrow, s1 = s0 + 8;
    float* d0 = g_attn + ((size_t)bI * SSEQ + s0) * DD + h * DHH + 2*lc;
    float* d1 = g_attn + ((size_t)bI * SSEQ + s1) * DD + h * DHH + 2*lc;
    #pragma unroll
    for (int nf = 0; nf < 8; nf++) {
        float2 w0, w1;
        w0.x = o[nf][0] * inv0; w0.y = o[nf][1] * inv0;
        w1.x = o[nf][2] * inv1; w1.y = o[nf][3] * inv1;
        *(float2*)(d0 + nf*8) = w0;
        *(float2*)(d1 + nf*8) = w1;
    }
}

// ---------------------------------------------------------------------------
extern "C" void kernel_launch(void* const* d_in, const int* in_sizes, int n_in,
                              void* d_out, int out_size) {
    const float* x    = (const float*)d_in[0];
    const int*   mask = (const int*)  d_in[1];
    const float* Wqkv = (const float*)d_in[2];
    const float* bqkv = (const float*)d_in[3];
    const float* Wo   = (const float*)d_in[4];
    const float* bo   = (const float*)d_in[5];
    float* out = (float*)d_out;

    cudaFuncSetAttribute(attn_mma, cudaFuncAttributeMaxDynamicSharedMemorySize,
                         ATTN_SMEM_BYTES);
    cudaFuncSetAttribute(qkv_mma, cudaFuncAttributeMaxDynamicSharedMemorySize,
                         GEMM_SMEM_BYTES);
    cudaFuncSetAttribute(out_mma, cudaFuncAttributeMaxDynamicSharedMemorySize,
                         GEMM_SMEM_BYTES);

    compact_b<<<BB, 1024>>>(mask);
    qkv_mma<<<dim3(E3/128, (BB*SSEQ)/128), 256, GEMM_SMEM_BYTES>>>(x, Wqkv, bqkv);
    attn_mma<<<dim3(BB*HH, SSEQ/128), 256, ATTN_SMEM_BYTES>>>();
    out_mma<<<dim3(DD/128, (BB*SSEQ)/128), 256, GEMM_SMEM_BYTES>>>(Wo, bo, out);
}

// round 12
// speedup vs baseline: 1.0255x; 1.0255x over previous
#include <cuda_runtime.h>
#include <math.h>
#include <stdint.h>

#define BB   4
#define SSEQ 2048
#define DD   512
#define HH   8
#define DHH  64
#define E3   1536

// Scratch (allocation-free rule: __device__ globals)
__device__ float g_q[BB*HH*SSEQ*DHH];    // [b,h,s,dh]
__device__ float g_k[BB*HH*SSEQ*DHH];
__device__ float g_v[BB*HH*SSEQ*DHH];
__device__ float g_attn[BB*SSEQ*DD];     // [b,s,d]
__device__ int   g_cnt[BB];              // active-key count per batch
__device__ int   g_idx[BB*SSEQ];         // active key indices (unordered)

// ---------------------------------------------------------------------------
// TF32 mma.sync helpers (plain sm_80+ PTX)
// ---------------------------------------------------------------------------
__device__ __forceinline__ uint32_t f2tf32(float x) {
    uint32_t y;
    asm("cvt.rna.tf32.f32 %0, %1;" : "=r"(y) : "f"(x));
    return y;
}
// Register-time round-to-nearest for raw fp32 bits fed to tf32 MMA.
#define RNA(x) ((x) + 0x1000u)

__device__ __forceinline__ void mma_tf32(float (&d)[4], const uint32_t (&a)[4],
                                         const uint32_t (&b)[2]) {
    asm volatile("mma.sync.aligned.m16n8k8.row.col.f32.tf32.tf32.f32 "
                 "{%0,%1,%2,%3}, {%4,%5,%6,%7}, {%8,%9}, {%0,%1,%2,%3};"
                 : "+f"(d[0]), "+f"(d[1]), "+f"(d[2]), "+f"(d[3])
                 : "r"(a[0]), "r"(a[1]), "r"(a[2]), "r"(a[3]),
                   "r"(b[0]), "r"(b[1]));
}
__device__ __forceinline__ uint32_t smem_u32(const void* p) {
    uint32_t a;
    asm("{ .reg .u64 t; cvta.to.shared.u64 t, %1; cvt.u32.u64 %0, t; }"
        : "=r"(a) : "l"(p));
    return a;
}

// Fast 2^x for x <= 0 on the FMA pipe (no MUFU). Rel err ~4e-5.
__device__ __forceinline__ float fexp2(float x) {
    x = fmaxf(x, -126.0f);
    const float z = x + 12582912.0f;                       // 1.5*2^23
    const int   n = (__float_as_int(z) & 0x7FFFFF) - 0x400000;
    const float f = x - (z - 12582912.0f);
    float p = fmaf(fmaf(fmaf(fmaf(0.00961813f, f, 0.05550411f),
                             f, 0.24022651f), f, 0.69314718f), f, 1.0f);
    return __int_as_float(__float_as_int(p) + (n << 23));
}

// ---------------------------------------------------------------------------
// Projection GEMMs: 128x128 CTA tile, 8 warps (2M x 4N), warp tile 64x32.
// cp.async 3-stage pipeline with ONE barrier per chunk:
//   wait(ch) -> sync -> prefetch(ch+2) -> compute(ch).
// Stage ch%3 is only rewritten by prefetch(ch+3), which every warp issues
// after the NEXT barrier, i.e. after all warps finished compute(ch).
// ---------------------------------------------------------------------------
#define GST 36
#define KC  32
#define NCH (DD/KC)          // 16 chunks
#define NST 3                // pipeline stages
#define GEMM_TILE_U32 (128*GST)
#define GEMM_SMEM_BYTES (NST * 2 * GEMM_TILE_U32 * 4)   // 110592

__device__ __forceinline__ void gemm_prefetch(const float* __restrict__ Ag,
                                              const float* __restrict__ Bg,
                                              int ch, uint32_t a_byte,
                                              uint32_t b_byte, int tid) {
    const uint32_t so = (uint32_t)((ch % NST) * 2 * GEMM_TILE_U32 * 4);
    #pragma unroll
    for (int it = 0; it < 4; it++) {
        const int i = tid + it * 256;
        const int r = i >> 3;               // row 0..127
        const int c = (i & 7) * 16;         // byte chunk within 128B row
        const void* ga = (const char*)(Ag + (size_t)r * DD + ch * KC) + c;
        const void* gb = (const char*)(Bg + (size_t)r * DD + ch * KC) + c;
        const uint32_t da = a_byte + so + (uint32_t)r * (GST*4) + c;
        const uint32_t db = b_byte + so + (uint32_t)r * (GST*4) + c;
        asm volatile("cp.async.cg.shared.global [%0], [%1], 16;" :: "r"(da), "l"(ga));
        asm volatile("cp.async.cg.shared.global [%0], [%1], 16;" :: "r"(db), "l"(gb));
    }
    asm volatile("cp.async.commit_group;" ::: "memory");
}

__device__ __forceinline__ void mma_mainloop(const float* __restrict__ Ag,
                                             const float* __restrict__ Bg,
                                             uint32_t* smu,
                                             float acc[4][4][4]) {
    const int tid = threadIdx.x;
    const int wid = tid >> 5, lane = tid & 31;
    const int wm = wid >> 2, wn = wid & 3;
    const int lr = lane >> 2, lc = lane & 3;
    const uint32_t sb = smem_u32(smu);
    const uint32_t a_byte = sb;
    const uint32_t b_byte = sb + GEMM_TILE_U32 * 4;

    gemm_prefetch(Ag, Bg, 0, a_byte, b_byte, tid);
    gemm_prefetch(Ag, Bg, 1, a_byte, b_byte, tid);

    for (int ch = 0; ch < NCH; ch++) {
        asm volatile("cp.async.wait_group 1;" ::: "memory");   // chunk ch landed
        __syncthreads();
        if (ch + 2 < NCH)
            gemm_prefetch(Ag, Bg, ch + 2, a_byte, b_byte, tid);
        else
            asm volatile("cp.async.commit_group;" ::: "memory");  // empty group

        const uint32_t* As = smu + (ch % NST) * 2 * GEMM_TILE_U32;
        const uint32_t* Bs = As + GEMM_TILE_U32;

        #pragma unroll
        for (int ks = 0; ks < KC; ks += 8) {
            uint32_t a[4][4], b[4][2];
            #pragma unroll
            for (int mf = 0; mf < 4; mf++) {
                const uint32_t* p = As + (wm*64 + mf*16 + lr) * GST + ks + lc;
                a[mf][0] = RNA(p[0]);
                a[mf][1] = RNA(p[8*GST]);
                a[mf][2] = RNA(p[4]);
                a[mf][3] = RNA(p[8*GST + 4]);
            }
            #pragma unroll
            for (int nf = 0; nf < 4; nf++) {
                const uint32_t* p = Bs + (wn*32 + nf*8 + lr) * GST + ks + lc;
                b[nf][0] = RNA(p[0]);
                b[nf][1] = RNA(p[4]);
            }
            #pragma unroll
            for (int mf = 0; mf < 4; mf++)
                #pragma unroll
                for (int nf = 0; nf < 4; nf++)
                    mma_tf32(acc[mf][nf], a[mf], b[nf]);
        }
        // no trailing barrier: next iteration's wait+sync protects stage reuse
    }
}

__global__ __launch_bounds__(256, 2) void qkv_mma(const float* __restrict__ X,
                                                  const float* __restrict__ W,
                                                  const float* __restrict__ bias,
                                                  const int* __restrict__ mask) {
    extern __shared__ uint32_t smu[];
    // Fused mask compaction: 4 designated CTAs (exact: softmax is order-
    // invariant; dropped keys would carry weight exp(NEG - max) == 0).
    if (blockIdx.x == 0 && blockIdx.y < BB) {
        const int b = blockIdx.y;
        if (threadIdx.x == 0) g_cnt[b] = 0;
        __syncthreads();
        #pragma unroll
        for (int i = threadIdx.x; i < SSEQ; i += 256) {
            if (mask[b * SSEQ + i] != 0) {
                const int p = atomicAdd(&g_cnt[b], 1);
                g_idx[b * SSEQ + p] = i;
            }
        }
    }

    const int m0 = blockIdx.y << 7, n0 = blockIdx.x << 7;
    float acc[4][4][4] = {};
    mma_mainloop(X + (size_t)m0 * DD, W + (size_t)n0 * DD, smu, acc);

    const int tid = threadIdx.x;
    const int wid = tid >> 5, lane = tid & 31;
    const int wm = wid >> 2, wn = wid & 3;
    const int lr = lane >> 2, lc = lane & 3;

    #pragma unroll
    for (int mf = 0; mf < 4; mf++) {
        #pragma unroll
        for (int nf = 0; nf < 4; nf++) {
            const int cb = n0 + wn*32 + nf*8 + 2*lc;     // even
            const int h   = cb / 192;
            const int rr  = cb - h * 192;
            const int sel = rr >> 6;
            const int dh0 = rr & 63;
            float* gbase = (sel == 0 ? g_q : sel == 1 ? g_k : g_v);
            const float b0 = bias[cb], b1 = bias[cb + 1];
            #pragma unroll
            for (int half = 0; half < 2; half++) {
                const int row = m0 + wm*64 + mf*16 + lr + 8*half;
                const int bI = row >> 11, sI = row & (SSEQ - 1);
                float2 o;
                o.x = acc[mf][nf][2*half + 0] + b0;
                o.y = acc[mf][nf][2*half + 1] + b1;
                *(float2*)(gbase + ((size_t)(bI*HH + h)*SSEQ + sI)*DHH + dh0) = o;
            }
        }
    }
}

__global__ __launch_bounds__(256, 2) void out_mma(const float* __restrict__ W,
                                                  const float* __restrict__ bias,
                                                  float* __restrict__ Out) {
    extern __shared__ uint32_t smu[];
    const int m0 = blockIdx.y << 7, n0 = blockIdx.x << 7;
    float acc[4][4][4] = {};
    mma_mainloop(g_attn + (size_t)m0 * DD, W + (size_t)n0 * DD, smu, acc);

    const int tid = threadIdx.x;
    const int wid = tid >> 5, lane = tid & 31;
    const int wm = wid >> 2, wn = wid & 3;
    const int lr = lane >> 2, lc = lane & 3;

    #pragma unroll
    for (int mf = 0; mf < 4; mf++) {
        #pragma unroll
        for (int nf = 0; nf < 4; nf++) {
            const int cb = n0 + wn*32 + nf*8 + 2*lc;
            const float b0 = bias[cb], b1 = bias[cb + 1];
            #pragma unroll
            for (int half = 0; half < 2; half++) {
                const int row = m0 + wm*64 + mf*16 + lr + 8*half;
                float2 o;
                o.x = acc[mf][nf][2*half + 0] + b0;
                o.y = acc[mf][nf][2*half + 1] + b1;
                *(float2*)(Out + (size_t)row * DD + cb) = o;
            }
        }
    }
}

// ---------------------------------------------------------------------------
// Kernel 2: flash attention, tf32 mma.sync, warp tile 32 q-rows x 64 keys,
// cp.async double-buffered K/V pipeline. CTA = 8 warps = 256 q-rows.
// grid: (B*H = 32, S/256 = 8)    [round-10 proven version]
// ---------------------------------------------------------------------------
#define QST 68   // Qs/Ps row stride (conflict-free fragment access)
#define KST 68   // Ks row stride [key][dh]
#define VST 72   // Vs row stride [key][dh]; 72%32=8 -> conflict-free B frags

// Full-tile cp.async prefetch: 64 rows x 256 B each for K and V.
__device__ __forceinline__ void prefetch_tile(const float* Kbh, const float* Vbh,
                                              const int* idx, int t, int L,
                                              uint32_t ks_byte, uint32_t vs_byte,
                                              int tid) {
    const uint32_t bo = (uint32_t)((t & 1) * 64);
    #pragma unroll
    for (int it = 0; it < 4; it++) {
        const int i = tid + it * 256;
        const int r = i >> 4;               // key row 0..63
        const int ch = (i & 15) * 16;       // byte chunk within 256B row
        const int rr = (t << 6) + r;
        const int kr = idx[rr < L ? rr : L - 1];
        const void* gk = (const char*)(Kbh + (size_t)kr * DHH) + ch;
        const void* gv = (const char*)(Vbh + (size_t)kr * DHH) + ch;
        const uint32_t dk = ks_byte + (bo + (uint32_t)r) * (KST*4) + ch;
        const uint32_t dv = vs_byte + (bo + (uint32_t)r) * (VST*4) + ch;
        asm volatile("cp.async.cg.shared.global [%0], [%1], 16;" :: "r"(dk), "l"(gk));
        asm volatile("cp.async.cg.shared.global [%0], [%1], 16;" :: "r"(dv), "l"(gv));
    }
    asm volatile("cp.async.commit_group;" ::: "memory");
}

__global__ __launch_bounds__(256) void attn_mma() {
    extern __shared__ uint32_t smu[];
    uint32_t* Qs  = smu;                     // [256][QST] tf32
    uint32_t* Ps  = smu + 256*QST;           // [256][QST] tf32 weights
    uint32_t* KsB = smu + 512*QST;           // [2][64][KST] fp32 (raw)
    uint32_t* VsB = KsB + 2*64*KST;          // [2][64][VST] fp32 (raw)
    const uint32_t sb = smem_u32(smu);
    const uint32_t ks_byte = sb + 512*QST*4;
    const uint32_t vs_byte = ks_byte + 2*64*KST*4;

    const int tid = threadIdx.x;
    const int wid = tid >> 5, lane = tid & 31;
    const int lr = lane >> 2, lc = lane & 3;
    const int bh = blockIdx.x;
    const int bI = bh >> 3, h = bh & 7;
    const int q0 = blockIdx.y << 8;
    const int L  = g_cnt[bI];
    const int* idx = g_idx + bI * SSEQ;
    const float* Kbh = g_k + (size_t)bh * SSEQ * DHH;
    const float* Vbh = g_v + (size_t)bh * SSEQ * DHH;
    const int nT = (L + 63) >> 6;

    prefetch_tile(Kbh, Vbh, idx, 0, L, ks_byte, vs_byte, tid);

    // Load Q tile (256 x 64) as tf32 (overlaps with cp.async flight)
    const float* Qg = g_q + ((size_t)bh * SSEQ + q0) * DHH;
    #pragma unroll
    for (int it = 0; it < 16; it++) {
        const int i = tid + it * 256;
        const int r = i >> 4, c4 = (i & 15) << 2;
        const float4 v = *(const float4*)(Qg + r * DHH + c4);
        uint32_t* p = Qs + r * QST + c4;
        p[0] = f2tf32(v.x); p[1] = f2tf32(v.y);
        p[2] = f2tf32(v.z); p[3] = f2tf32(v.w);
    }

    float o[2][8][4] = {};
    float mrow[2][2], lrow[2][2];
    mrow[0][0] = mrow[0][1] = mrow[1][0] = mrow[1][1] = -3.0e38f;
    lrow[0][0] = lrow[0][1] = lrow[1][0] = lrow[1][1] = 0.f;
    const float C = 0.18033688f;   // (1/sqrt(64)) * log2(e)
    const int base = wid << 5;     // warp's first q-row (32 rows per warp)

    for (int t = 0; t < nT; t++) {
        prefetch_tile(Kbh, Vbh, idx, (t + 1 < nT) ? t + 1 : nT - 1, L,
                      ks_byte, vs_byte, tid);
        asm volatile("cp.async.wait_group 1;" ::: "memory");   // tile t landed
        __syncthreads();

        const uint32_t* Kc = KsB + (t & 1) * 64 * KST;
        const uint32_t* Vc = VsB + (t & 1) * 64 * VST;
        const int k0 = t << 6;

        // S = Q K^T  (per warp: 32 rows x 64 keys; B frags shared by 2 blocks)
        float s[2][8][4] = {};
        #pragma unroll
        for (int ks = 0; ks < 8; ks++) {
            uint32_t a[2][4];
            #pragma unroll
            for (int mf = 0; mf < 2; mf++) {
                const uint32_t* pa = Qs + (base + mf*16 + lr) * QST + ks*8 + lc;
                a[mf][0] = pa[0];
                a[mf][1] = pa[8*QST];
                a[mf][2] = pa[4];
                a[mf][3] = pa[8*QST + 4];
            }
            #pragma unroll
            for (int nf = 0; nf < 8; nf++) {
                uint32_t b[2];
                const uint32_t* pb = Kc + (nf*8 + lr) * KST + ks*8 + lc;
                b[0] = pb[0];
                b[1] = pb[4];
                mma_tf32(s[0][nf], a[0], b);
                mma_tf32(s[1][nf], a[1], b);
            }
        }

        // Scale + mask padding columns
        #pragma unroll
        for (int nf = 0; nf < 8; nf++) {
            const int cb = k0 + nf*8 + 2*lc;
            const bool v0 = cb < L, v1 = (cb + 1) < L;
            #pragma unroll
            for (int mf = 0; mf < 2; mf++) {
                s[mf][nf][0] = v0 ? s[mf][nf][0]*C : -3.0e38f;
                s[mf][nf][1] = v1 ? s[mf][nf][1]*C : -3.0e38f;
                s[mf][nf][2] = v0 ? s[mf][nf][2]*C : -3.0e38f;
                s[mf][nf][3] = v1 ? s[mf][nf][3]*C : -3.0e38f;
            }
        }

        // Online softmax per row block
        #pragma unroll
        for (int mf = 0; mf < 2; mf++) {
            float pm0 = -3.0e38f, pm1 = -3.0e38f;
            #pragma unroll
            for (int nf = 0; nf < 8; nf++) {
                pm0 = fmaxf(pm0, fmaxf(s[mf][nf][0], s[mf][nf][1]));
                pm1 = fmaxf(pm1, fmaxf(s[mf][nf][2], s[mf][nf][3]));
            }
            pm0 = fmaxf(pm0, __shfl_xor_sync(0xffffffffu, pm0, 1));
            pm0 = fmaxf(pm0, __shfl_xor_sync(0xffffffffu, pm0, 2));
            pm1 = fmaxf(pm1, __shfl_xor_sync(0xffffffffu, pm1, 1));
            pm1 = fmaxf(pm1, __shfl_xor_sync(0xffffffffu, pm1, 2));

            const float mn0 = fmaxf(mrow[mf][0], pm0);
            const float mn1 = fmaxf(mrow[mf][1], pm1);
            const float al0 = fexp2(mrow[mf][0] - mn0);
            const float al1 = fexp2(mrow[mf][1] - mn1);
            mrow[mf][0] = mn0; mrow[mf][1] = mn1;

            float sum0 = 0.f, sum1 = 0.f;
            uint32_t* Pw0 = Ps + (base + mf*16 + lr) * QST + 2*lc;
            uint32_t* Pw1 = Pw0 + 8*QST;
            #pragma unroll
            for (int nf = 0; nf < 8; nf++) {
                const float p0 = fexp2(s[mf][nf][0] - mn0);
                const float p1 = fexp2(s[mf][nf][1] - mn0);
                const float p2 = fexp2(s[mf][nf][2] - mn1);
                const float p3 = fexp2(s[mf][nf][3] - mn1);
                sum0 += p0 + p1;
                sum1 += p2 + p3;
                Pw0[nf*8 + 0] = f2tf32(p0);
                Pw0[nf*8 + 1] = f2tf32(p1);
                Pw1[nf*8 + 0] = f2tf32(p2);
                Pw1[nf*8 + 1] = f2tf32(p3);
            }
            sum0 += __shfl_xor_sync(0xffffffffu, sum0, 1);
            sum0 += __shfl_xor_sync(0xffffffffu, sum0, 2);
            sum1 += __shfl_xor_sync(0xffffffffu, sum1, 1);
            sum1 += __shfl_xor_sync(0xffffffffu, sum1, 2);
            lrow[mf][0] = lrow[mf][0] * al0 + sum0;
            lrow[mf][1] = lrow[mf][1] * al1 + sum1;

            #pragma unroll
            for (int nf = 0; nf < 8; nf++) {
                o[mf][nf][0] *= al0; o[mf][nf][1] *= al0;
                o[mf][nf][2] *= al1; o[mf][nf][3] *= al1;
            }
        }
        __syncwarp();   // P written by this warp, read by this warp's lanes

        // O += P V   (B frags from Vc[key][dh], shared by 2 row blocks)
        #pragma unroll
        for (int ks = 0; ks < 8; ks++) {
            uint32_t a[2][4];
            #pragma unroll
            for (int mf = 0; mf < 2; mf++) {
                const uint32_t* pa = Ps + (base + mf*16 + lr) * QST + ks*8 + lc;
                a[mf][0] = pa[0];
                a[mf][1] = pa[8*QST];
                a[mf][2] = pa[4];
                a[mf][3] = pa[8*QST + 4];
            }
            #pragma unroll
            for (int nf = 0; nf < 8; nf++) {
                uint32_t b[2];
                const uint32_t* pb = Vc + (ks*8 + lc) * VST + nf*8 + lr;
                b[0] = pb[0];
                b[1] = pb[4*VST];
                mma_tf32(o[0][nf], a[0], b);
                mma_tf32(o[1][nf], a[1], b);
            }
        }
        __syncthreads();   // all reads of buf t&1 done before t+1 prefetch hits it
    }

    // Epilogue: normalize and write [b,s,d]
    #pragma unroll
    for (int mf = 0; mf < 2; mf++) {
        const float inv0 = 1.f / lrow[mf][0], inv1 = 1.f / lrow[mf][1];
        const int s0 = q0 + base + mf*16 + lr, s1 = s0 + 8;
        float* d0 = g_attn + ((size_t)bI * SSEQ + s0) * DD + h * DHH + 2*lc;
        float* d1 = g_attn + ((size_t)bI * SSEQ + s1) * DD + h * DHH + 2*lc;
        #pragma unroll
        for (int nf = 0; nf < 8; nf++) {
            float2 w0, w1;
            w0.x = o[mf][nf][0] * inv0; w0.y = o[mf][nf][1] * inv0;
            w1.x = o[mf][nf][2] * inv1; w1.y = o[mf][nf][3] * inv1;
            *(float2*)(d0 + nf*8) = w0;
            *(float2*)(d1 + nf*8) = w1;
        }
    }
}

// ---------------------------------------------------------------------------
extern "C" void kernel_launch(void* const* d_in, const int* in_sizes, int n_in,
                              void* d_out, int out_size) {
    const float* x    = (const float*)d_in[0];
    const int*   mask = (const int*)  d_in[1];
    const float* Wqkv = (const float*)d_in[2];
    const float* bqkv = (const float*)d_in[3];
    const float* Wo   = (const float*)d_in[4];
    const float* bo   = (const float*)d_in[5];
    float* out = (float*)d_out;

    const int attn_smem = (512*QST + 2*64*KST + 2*64*VST) * (int)sizeof(uint32_t);
    cudaFuncSetAttribute(attn_mma, cudaFuncAttributeMaxDynamicSharedMemorySize,
                         attn_smem);
    cudaFuncSetAttribute(qkv_mma, cudaFuncAttributeMaxDynamicSharedMemorySize,
                         GEMM_SMEM_BYTES);
    cudaFuncSetAttribute(out_mma, cudaFuncAttributeMaxDynamicSharedMemorySize,
                         GEMM_SMEM_BYTES);

    qkv_mma<<<dim3(E3/128, (BB*SSEQ)/128), 256, GEMM_SMEM_BYTES>>>(x, Wqkv, bqkv, mask);
    attn_mma<<<dim3(BB*HH, SSEQ/256), 256, attn_smem>>>();
    out_mma<<<dim3(DD/128, (BB*SSEQ)/128), 256, GEMM_SMEM_BYTES>>>(Wo, bo, out);
}